// round 8
// baseline (speedup 1.0000x reference)
#include <cuda_runtime.h>
#include <cuda_bf16.h>
#include <math.h>

// Problem constants
#define B_  16
#define T_  12
#define N_  325
#define D_  64
#define L_  2
#define G_  192
#define BN  (B_ * N_)          // 5200

// d_out layout (floats): output, hidden, attn_input, attn_hidden
#define SZ_OUT ((size_t)B_ * T_ * N_ * D_)
#define SZ_HID ((size_t)B_ * L_ * N_ * D_)
#define SZ_A   ((size_t)B_ * T_ * L_ * N_ * N_)
#define OFF_OUT 0
#define OFF_HID (SZ_OUT)
#define OFF_AI  (SZ_OUT + SZ_HID)
#define OFF_AH  (SZ_OUT + SZ_HID + SZ_A)

// Scratch (K1/K2 alternate in stream order -> no double buffering needed)
__device__ float g_X[BN * D_];
__device__ float g_Q[2][BN * D_];
__device__ float g_K[2][BN * D_];
__device__ float g_O[2][BN * G_];

typedef unsigned long long ull;

__device__ __forceinline__ void ffma2(ull& d, ull a, ull b) {
    asm volatile("fma.rn.f32x2 %0, %1, %2, %0;" : "+l"(d) : "l"(a), "l"(b));
}
__device__ __forceinline__ float f2sum(ull v) {
    float lo, hi;
    asm("mov.b64 {%0, %1}, %2;" : "=f"(lo), "=f"(hi) : "l"(v));
    return lo + hi;
}
__device__ __forceinline__ ull dup2(float v) {
    ull r;
    asm("mov.b64 %0, {%1, %1};" : "=l"(r) : "f"(v));
    return r;
}
__device__ __forceinline__ void unpk(ull v, float& lo, float& hi) {
    asm("mov.b64 {%0, %1}, %2;" : "=f"(lo), "=f"(hi) : "l"(v));
}

// ---------------------------------------------------------------------------
__global__ void zero_hidden_kernel(float* __restrict__ outf) {
    size_t i = (size_t)blockIdx.x * blockDim.x + threadIdx.x;
    if (i < SZ_HID) outf[OFF_HID + i] = 0.0f;
}

// ---------------------------------------------------------------------------
// K1: attention per (tile, gat, batch). grid (14, 2, 16), block 256.
// RT=24 rows; warp w owns rows w, w+8, w+16.
// ---------------------------------------------------------------------------
#define RT     24
#define NT     14
#define NPADS  352
#define QSTR   68
#define KSTR   66
#define K1_S   (RT * QSTR)                 // 1632
#define K1_CH  (K1_S + RT * NPADS)         // 1632 + 8448 = 10080
#define K1_SMEM_FLOATS (K1_CH + 64 * KSTR) // + 4224 = 14304 -> 57,216 B

__global__ __launch_bounds__(256, 4)
void attn_kernel(int t, int l, int from_x,
                 const float* __restrict__ x,
                 const float* __restrict__ Wv_i, const float* __restrict__ Wv_h,
                 const float* __restrict__ b_i,  const float* __restrict__ b_h,
                 float* __restrict__ outf) {
    extern __shared__ float sm[];
    float* Qs = sm;               // RT x QSTR  (Q, then PX)
    float* S  = sm + K1_S;        // RT x NPADS (scores/P, then Wt passes)
    float* CH = sm + K1_CH;       // 64 x KSTR  (K / x chunks)

    const int rt   = blockIdx.x;
    const int g    = blockIdx.y;
    const int b    = blockIdx.z;
    const int tid  = threadIdx.x;
    const int w    = tid >> 5;
    const int lane = tid & 31;
    const int r0   = rt * RT;

    const float* Qg = g_Q[g] + (size_t)b * N_ * D_;
    const float* Kg = g_K[g] + (size_t)b * N_ * D_;
    const float* xsrc = from_x ? x + (((size_t)b * T_ + t) * N_) * D_
                               : g_X + (size_t)b * N_ * D_;

    // ---- load Q tile ----
    for (int idx = tid; idx < RT * 64; idx += 256) {
        int r = idx >> 6, d = idx & 63;
        int qr = r0 + r;
        Qs[r * QSTR + d] = (qr < N_) ? Qg[(size_t)qr * D_ + d] : 0.0f;
    }

    // ---- Phase 1: S = Q K^T / 8 ----
    for (int kc = 0; kc < 6; kc++) {
        const int kb = kc * 64;
        __syncthreads();
        for (int idx = tid; idx < 64 * 16; idx += 256) {
            int key = idx >> 4, d4 = idx & 15;
            int gk = kb + key;
            float4 v = make_float4(0.f, 0.f, 0.f, 0.f);
            if (gk < N_) v = *(const float4*)(Kg + (size_t)gk * D_ + 4 * d4);
            int bs = key * KSTR + 4 * d4;
            *(float2*)&CH[bs]     = make_float2(v.x, v.y);
            *(float2*)&CH[bs + 2] = make_float2(v.z, v.w);
        }
        __syncthreads();

        ull acc[3][2] = {};
#pragma unroll
        for (int k = 0; k < 64; k += 4) {
            ulonglong2 q[3];
#pragma unroll
            for (int m = 0; m < 3; m++)
                q[m] = *(const ulonglong2*)&Qs[(w + 8 * m) * QSTR + k];
#pragma unroll
            for (int j = 0; j < 2; j++) {
                const int c = lane + 32 * j;
                ull k0 = *(const ull*)&CH[c * KSTR + k];
                ull k1 = *(const ull*)&CH[c * KSTR + k + 2];
#pragma unroll
                for (int m = 0; m < 3; m++) {
                    ffma2(acc[m][j], q[m].x, k0);
                    ffma2(acc[m][j], q[m].y, k1);
                }
            }
        }
#pragma unroll
        for (int j = 0; j < 2; j++) {
            int c = kb + lane + 32 * j;
            if (c < NPADS) {
#pragma unroll
                for (int m = 0; m < 3; m++)
                    S[(w + 8 * m) * NPADS + c] = f2sum(acc[m][j]) * 0.125f;
            }
        }
    }
    __syncthreads();

    // ---- Softmax + write attn to d_out ----
    const size_t attn_base = (g == 0 ? OFF_AI : OFF_AH);
    for (int rr = w; rr < RT; rr += 8) {
        int qr = r0 + rr;
        if (qr < N_) {
            float mx = -1e30f;
            for (int i = lane; i < N_; i += 32) mx = fmaxf(mx, S[rr * NPADS + i]);
#pragma unroll
            for (int o = 16; o; o >>= 1) mx = fmaxf(mx, __shfl_xor_sync(0xffffffffu, mx, o));
            float s = 0.0f;
            for (int i = lane; i < NPADS; i += 32) {
                if (i < N_) {
                    float e = __expf(S[rr * NPADS + i] - mx);
                    S[rr * NPADS + i] = e;
                    s += e;
                } else S[rr * NPADS + i] = 0.0f;
            }
#pragma unroll
            for (int o = 16; o; o >>= 1) s += __shfl_xor_sync(0xffffffffu, s, o);
            float inv = 1.0f / s;
            float* arow = outf + attn_base +
                ((((size_t)b * T_ + t) * L_ + l) * N_ + qr) * (size_t)N_;
            for (int i = lane; i < N_; i += 32) {
                float p = S[rr * NPADS + i] * inv;
                S[rr * NPADS + i] = p;
                arow[i] = p;
            }
        } else {
            for (int i = lane; i < NPADS; i += 32) S[rr * NPADS + i] = 0.0f;
        }
    }

    // ---- Phase 2: PX = P @ x ----
    // last chunk reads S cols up to 383: beyond NPADS but lands in CH region
    // (allocated); those x values are 0 so the products contribute 0.
    ull acc2[3] = {};
    for (int kc = 0; kc < 6; kc++) {
        const int kb = kc * 64;
        __syncthreads();
        for (int idx = tid; idx < 64 * 16; idx += 256) {
            int key = idx >> 4, d4 = idx & 15;
            int gk = kb + key;
            float4 v = make_float4(0.f, 0.f, 0.f, 0.f);
            if (gk < N_) v = *(const float4*)(xsrc + (size_t)gk * D_ + 4 * d4);
            int bs = key * KSTR + 4 * d4;
            *(float2*)&CH[bs]     = make_float2(v.x, v.y);
            *(float2*)&CH[bs + 2] = make_float2(v.z, v.w);
        }
        __syncthreads();
#pragma unroll 4
        for (int kk = 0; kk < 64; kk += 4) {
            float4 p[3];
#pragma unroll
            for (int m = 0; m < 3; m++)
                p[m] = *(const float4*)&S[(w + 8 * m) * NPADS + kb + kk];
            ull xv0 = *(const ull*)&CH[(kk)     * KSTR + 2 * lane];
            ull xv1 = *(const ull*)&CH[(kk + 1) * KSTR + 2 * lane];
            ull xv2 = *(const ull*)&CH[(kk + 2) * KSTR + 2 * lane];
            ull xv3 = *(const ull*)&CH[(kk + 3) * KSTR + 2 * lane];
#pragma unroll
            for (int m = 0; m < 3; m++) {
                ffma2(acc2[m], dup2(p[m].x), xv0);
                ffma2(acc2[m], dup2(p[m].y), xv1);
                ffma2(acc2[m], dup2(p[m].z), xv2);
                ffma2(acc2[m], dup2(p[m].w), xv3);
            }
        }
    }
    __syncthreads();
#pragma unroll
    for (int m = 0; m < 3; m++) {
        float lo, hi;
        unpk(acc2[m], lo, hi);
        *(float2*)&Qs[(w + 8 * m) * QSTR + 2 * lane] = make_float2(lo, hi);
    }

    // ---- Phase 3: O = PX @ Wv + bias -> g_O (3 passes of 64 cols) ----
    const float* W    = (g ? Wv_h : Wv_i) + (size_t)l * D_ * G_;
    const float* bias = (g ? b_h : b_i) + (size_t)l * G_;
    float* Og = g_O[g] + (size_t)b * N_ * G_;
    float* Wt = S;                         // 64 x KSTR per pass (fits in S)

    for (int jg = 0; jg < 3; jg++) {
        __syncthreads();
        for (int idx = tid; idx < 64 * 64; idx += 256) {
            int d = idx >> 6, c = idx & 63;
            Wt[c * KSTR + d] = W[d * G_ + jg * 64 + c];
        }
        __syncthreads();

        ull acc3[3][2] = {};
#pragma unroll
        for (int d = 0; d < 64; d += 4) {
            ulonglong2 px[3];
#pragma unroll
            for (int m = 0; m < 3; m++)
                px[m] = *(const ulonglong2*)&Qs[(w + 8 * m) * QSTR + d];
#pragma unroll
            for (int j = 0; j < 2; j++) {
                const int c = lane + 32 * j;
                ull w0 = *(const ull*)&Wt[c * KSTR + d];
                ull w1 = *(const ull*)&Wt[c * KSTR + d + 2];
#pragma unroll
                for (int m = 0; m < 3; m++) {
                    ffma2(acc3[m][j], px[m].x, w0);
                    ffma2(acc3[m][j], px[m].y, w1);
                }
            }
        }
#pragma unroll
        for (int m = 0; m < 3; m++) {
            int qr = r0 + w + 8 * m;
            if (qr < N_) {
#pragma unroll
                for (int j = 0; j < 2; j++) {
                    int col = jg * 64 + lane + 32 * j;
                    Og[(size_t)qr * G_ + col] = f2sum(acc3[m][j]) + __ldg(&bias[col]);
                }
            }
        }
    }
}

// ---------------------------------------------------------------------------
// K2: GRU gate + LayerNorm + next-stage Q/K. grid (14, 16), block 256.
// do_gate=0: prologue (QK from x[:,tx] only).
// l_next==0 -> QK input is x[:,tx]; l_next==1 -> QK input is this stage's y.
// ---------------------------------------------------------------------------
#define K2_WT (RT * QSTR)                       // 1632
#define K2_SMEM_FLOATS (K2_WT + 4 * 64 * KSTR)  // 1632 + 16896 = 18528 -> 74,112 B

__global__ __launch_bounds__(256, 3)
void gate_qk_kernel(int t, int l, int do_gate, int do_qk, int l_next, int tx,
                    const float* __restrict__ x,
                    const float* __restrict__ Wq_i, const float* __restrict__ Wk_i,
                    const float* __restrict__ Wq_h, const float* __restrict__ Wk_h,
                    const float* __restrict__ ln_g, const float* __restrict__ ln_b,
                    float* __restrict__ outf) {
    extern __shared__ float sm[];
    float* Ys = sm;             // RT x QSTR
    float* Wt = sm + K2_WT;     // 4 x (64 x KSTR): Wq0, Wk0, Wq1, Wk1

    const int rt   = blockIdx.x;
    const int b    = blockIdx.y;
    const int tid  = threadIdx.x;
    const int w    = tid >> 5;
    const int lane = tid & 31;
    const int r0   = rt * RT;

    if (do_gate) {
        for (int rr = w; rr < RT; rr += 8) {
            int qr = r0 + rr;
            float o0 = 0.0f, o1 = 0.0f;
            float* hid = 0;
            if (qr < N_) {
                const float* oi = g_O[0] + ((size_t)b * N_ + qr) * G_;
                const float* oh = g_O[1] + ((size_t)b * N_ + qr) * G_;
                hid = outf + OFF_HID + (((size_t)b * L_ + l) * N_ + qr) * D_;
                int d0 = lane, d1 = lane + 32;
                float h0 = hid[d0], h1 = hid[d1];
                float rg0 = 1.0f / (1.0f + expf(-(oi[d0]       + oh[d0])));
                float ig0 = 1.0f / (1.0f + expf(-(oi[64 + d0]  + oh[64 + d0])));
                float ng0 = tanhf(oi[128 + d0] + rg0 * oh[128 + d0]);
                o0 = ng0 + ig0 * (h0 - ng0);
                float rg1 = 1.0f / (1.0f + expf(-(oi[d1]       + oh[d1])));
                float ig1 = 1.0f / (1.0f + expf(-(oi[64 + d1]  + oh[64 + d1])));
                float ng1 = tanhf(oi[128 + d1] + rg1 * oh[128 + d1]);
                o1 = ng1 + ig1 * (h1 - ng1);
            }
            float s = o0 + o1, q = o0 * o0 + o1 * o1;
#pragma unroll
            for (int off = 16; off; off >>= 1) {
                s += __shfl_xor_sync(0xffffffffu, s, off);
                q += __shfl_xor_sync(0xffffffffu, q, off);
            }
            if (qr < N_) {
                float mu  = s * (1.0f / 64.0f);
                float var = q * (1.0f / 64.0f) - mu * mu;
                float rs  = rsqrtf(var + 1e-5f);
                int d0 = lane, d1 = lane + 32;
                float y0 = (o0 - mu) * rs * __ldg(&ln_g[l * D_ + d0]) + __ldg(&ln_b[l * D_ + d0]);
                float y1 = (o1 - mu) * rs * __ldg(&ln_g[l * D_ + d1]) + __ldg(&ln_b[l * D_ + d1]);
                hid[d0] = y0; hid[d1] = y1;
                float* gx = g_X + ((size_t)b * N_ + qr) * D_;
                gx[d0] = y0; gx[d1] = y1;
                if (l == L_ - 1) {
                    float* po = outf + OFF_OUT + (((size_t)b * T_ + t) * N_ + qr) * D_;
                    po[d0] = y0; po[d1] = y1;
                }
                Ys[rr * QSTR + d0] = y0; Ys[rr * QSTR + d1] = y1;
            } else {
                Ys[rr * QSTR + lane] = 0.0f; Ys[rr * QSTR + lane + 32] = 0.0f;
            }
        }
    }

    if (!do_qk) return;
    __syncthreads();

    if (l_next == 0) {
        const float* xn = x + (((size_t)b * T_ + tx) * N_) * D_;
        for (int idx = tid; idx < RT * 64; idx += 256) {
            int r = idx >> 6, d = idx & 63;
            int qr = r0 + r;
            Ys[r * QSTR + d] = (qr < N_) ? xn[(size_t)qr * D_ + d] : 0.0f;
        }
    }
    // stage transposed weights: mat 0:Wq0 1:Wk0 2:Wq1 3:Wk1
    for (int idx = tid; idx < 4 * 64 * 64; idx += 256) {
        int mat = idx >> 12;
        int r = (idx >> 6) & 63, c = idx & 63;
        const float* Ws = (mat == 0) ? Wq_i : (mat == 1) ? Wk_i : (mat == 2) ? Wq_h : Wk_h;
        Wt[mat * (64 * KSTR) + c * KSTR + r] = Ws[(size_t)l_next * D_ * D_ + r * 64 + c];
    }
    __syncthreads();

#pragma unroll
    for (int g = 0; g < 2; g++) {
        const float* WtQ = Wt + (2 * g)     * (64 * KSTR);
        const float* WtK = Wt + (2 * g + 1) * (64 * KSTR);
        ull aq[3][2] = {}, ak[3][2] = {};
#pragma unroll
        for (int d = 0; d < 64; d += 4) {
            ulonglong2 y4[3];
#pragma unroll
            for (int m = 0; m < 3; m++)
                y4[m] = *(const ulonglong2*)&Ys[(w + 8 * m) * QSTR + d];
#pragma unroll
            for (int j = 0; j < 2; j++) {
                const int c = lane + 32 * j;
                ull wq0 = *(const ull*)&WtQ[c * KSTR + d];
                ull wq1 = *(const ull*)&WtQ[c * KSTR + d + 2];
                ull wk0 = *(const ull*)&WtK[c * KSTR + d];
                ull wk1 = *(const ull*)&WtK[c * KSTR + d + 2];
#pragma unroll
                for (int m = 0; m < 3; m++) {
                    ffma2(aq[m][j], y4[m].x, wq0);
                    ffma2(aq[m][j], y4[m].y, wq1);
                    ffma2(ak[m][j], y4[m].x, wk0);
                    ffma2(ak[m][j], y4[m].y, wk1);
                }
            }
        }
        float* Qd = g_Q[g] + (size_t)b * N_ * D_;
        float* Kd = g_K[g] + (size_t)b * N_ * D_;
#pragma unroll
        for (int m = 0; m < 3; m++) {
            int qr = r0 + w + 8 * m;
            if (qr < N_) {
#pragma unroll
                for (int j = 0; j < 2; j++) {
                    Qd[(size_t)qr * D_ + lane + 32 * j] = f2sum(aq[m][j]);
                    Kd[(size_t)qr * D_ + lane + 32 * j] = f2sum(ak[m][j]);
                }
            }
        }
    }
}

// ---------------------------------------------------------------------------
extern "C" void kernel_launch(void* const* d_in, const int* in_sizes, int n_in,
                              void* d_out, int out_size) {
    const float* x    = (const float*)d_in[0];
    const float* Wq_i = (const float*)d_in[1];
    const float* Wk_i = (const float*)d_in[2];
    const float* Wv_i = (const float*)d_in[3];
    const float* b_i  = (const float*)d_in[4];
    const float* Wq_h = (const float*)d_in[5];
    const float* Wk_h = (const float*)d_in[6];
    const float* Wv_h = (const float*)d_in[7];
    const float* b_h  = (const float*)d_in[8];
    const float* ln_g = (const float*)d_in[9];
    const float* ln_b = (const float*)d_in[10];
    float* outf = (float*)d_out;

    const int k1_smem = K1_SMEM_FLOATS * (int)sizeof(float);  // 57,216 B
    const int k2_smem = K2_SMEM_FLOATS * (int)sizeof(float);  // 74,112 B
    cudaFuncSetAttribute(attn_kernel, cudaFuncAttributeMaxDynamicSharedMemorySize, k1_smem);
    cudaFuncSetAttribute(gate_qk_kernel, cudaFuncAttributeMaxDynamicSharedMemorySize, k2_smem);

    zero_hidden_kernel<<<(int)((SZ_HID + 255) / 256), 256>>>(outf);

    dim3 k1_grid(NT, 2, 16);
    dim3 k2_grid(NT, 16);

    // prologue: Q/K for stage (0,0) from x
    gate_qk_kernel<<<k2_grid, 256, k2_smem>>>(0, 0, /*do_gate*/0, /*do_qk*/1,
                                              /*l_next*/0, /*tx*/0, x,
                                              Wq_i, Wk_i, Wq_h, Wk_h, ln_g, ln_b, outf);

    for (int s = 0; s < T_ * L_; s++) {
        int t = s >> 1, l = s & 1;
        attn_kernel<<<k1_grid, 256, k1_smem>>>(t, l, (l == 0) ? 1 : 0, x,
                                               Wv_i, Wv_h, b_i, b_h, outf);
        gate_qk_kernel<<<k2_grid, 256, k2_smem>>>(t, l, 1, (s < T_ * L_ - 1) ? 1 : 0,
                                                  l ^ 1, t + 1, x,
                                                  Wq_i, Wk_i, Wq_h, Wk_h, ln_g, ln_b, outf);
    }
}

// round 9
// speedup vs baseline: 1.1864x; 1.1864x over previous
#include <cuda_runtime.h>
#include <cuda_bf16.h>
#include <math.h>

// Problem constants
#define B_  16
#define T_  12
#define N_  325
#define D_  64
#define L_  2
#define G_  192
#define BN  (B_ * N_)          // 5200

// d_out layout (floats): output, hidden, attn_input, attn_hidden
#define SZ_OUT ((size_t)B_ * T_ * N_ * D_)
#define SZ_HID ((size_t)B_ * L_ * N_ * D_)
#define SZ_A   ((size_t)B_ * T_ * L_ * N_ * N_)
#define OFF_OUT 0
#define OFF_HID (SZ_OUT)
#define OFF_AI  (SZ_OUT + SZ_HID)
#define OFF_AH  (SZ_OUT + SZ_HID + SZ_A)

// Scratch (launch order serializes producers/consumers)
__device__ float g_X[BN * D_];
__device__ float g_Q[2][BN * D_];
__device__ float g_K[2][BN * D_];
__device__ float g_O[2][BN * G_];

typedef unsigned long long ull;

__device__ __forceinline__ void ffma2(ull& d, ull a, ull b) {
    asm volatile("fma.rn.f32x2 %0, %1, %2, %0;" : "+l"(d) : "l"(a), "l"(b));
}
__device__ __forceinline__ float f2sum(ull v) {
    float lo, hi;
    asm("mov.b64 {%0, %1}, %2;" : "=f"(lo), "=f"(hi) : "l"(v));
    return lo + hi;
}
__device__ __forceinline__ ull dup2(float v) {
    ull r;
    asm("mov.b64 %0, {%1, %1};" : "=l"(r) : "f"(v));
    return r;
}

// ---------------------------------------------------------------------------
__global__ void zero_hidden_kernel(float* __restrict__ outf) {
    size_t i = (size_t)blockIdx.x * blockDim.x + threadIdx.x;
    if (i < SZ_HID) outf[OFF_HID + i] = 0.0f;
}

// ---------------------------------------------------------------------------
// K1: TALL attention. grid (4, 2, 16) = 128 CTAs, block 256, smem 176 KB.
// RT=88 rows; warp w owns rows w+8m, m<11 (11 rows/warp -> ~27 B/FFMA2).
//   P1: S = QK^T/8 (6 chunks of 64 keys, acc[11][2])
//   Softmax + attn write
//   P2: PX = P @ x (6 chunks, acc[11])
//   P3: O = PX @ Wv + bias -> g_O (Wv fully staged transposed, 3 col passes)
// ---------------------------------------------------------------------------
#define RT     88
#define NT     4
#define NPADS  384
#define QSTR   68
#define KSTR   66
#define SM_QS  0
#define SM_S   (RT * QSTR)                 // 5984
#define SM_CH  (SM_S + RT * NPADS)         // 5984 + 33792 = 39776
#define K1_SMEM_FLOATS (SM_CH + 64 * KSTR) // + 4224 = 44000 -> 176,000 B

__global__ __launch_bounds__(256, 1)
void attn_kernel(int t, int l, int from_x,
                 const float* __restrict__ x,
                 const float* __restrict__ Wv_i, const float* __restrict__ Wv_h,
                 const float* __restrict__ b_i,  const float* __restrict__ b_h,
                 float* __restrict__ outf) {
    extern __shared__ float sm[];
    float* Qs = sm + SM_QS;   // RT x QSTR   (Q, then PX)
    float* S  = sm + SM_S;    // RT x NPADS  (scores/P, then Wt 192x66)
    float* CH = sm + SM_CH;   // 64 x KSTR   (K / x chunks)

    const int rt   = blockIdx.x;
    const int g    = blockIdx.y;
    const int b    = blockIdx.z;
    const int tid  = threadIdx.x;
    const int w    = tid >> 5;
    const int lane = tid & 31;
    const int r0   = rt * RT;

    const float* Qg = g_Q[g] + (size_t)b * N_ * D_;
    const float* Kg = g_K[g] + (size_t)b * N_ * D_;
    const float* xsrc = from_x ? x + (((size_t)b * T_ + t) * N_) * D_
                               : g_X + (size_t)b * N_ * D_;

    // ---- load Q tile ----
    for (int idx = tid; idx < RT * 64; idx += 256) {
        int r = idx >> 6, d = idx & 63;
        int qr = r0 + r;
        Qs[r * QSTR + d] = (qr < N_) ? Qg[(size_t)qr * D_ + d] : 0.0f;
    }

    // ---- P1: S = Q K^T / 8 ----
    for (int kc = 0; kc < 6; kc++) {
        const int kb = kc * 64;
        __syncthreads();
        for (int idx = tid; idx < 64 * 16; idx += 256) {
            int key = idx >> 4, d4 = idx & 15;
            int gk = kb + key;
            float4 v = make_float4(0.f, 0.f, 0.f, 0.f);
            if (gk < N_) v = *(const float4*)(Kg + (size_t)gk * D_ + 4 * d4);
            int bs = key * KSTR + 4 * d4;
            *(float2*)&CH[bs]     = make_float2(v.x, v.y);
            *(float2*)&CH[bs + 2] = make_float2(v.z, v.w);
        }
        __syncthreads();

        ull acc[11][2] = {};
#pragma unroll
        for (int k = 0; k < 64; k += 4) {
            ulonglong2 q[11];
#pragma unroll
            for (int m = 0; m < 11; m++)
                q[m] = *(const ulonglong2*)&Qs[(w + 8 * m) * QSTR + k];
#pragma unroll
            for (int j = 0; j < 2; j++) {
                const int c = lane + 32 * j;
                ull k0 = *(const ull*)&CH[c * KSTR + k];
                ull k1 = *(const ull*)&CH[c * KSTR + k + 2];
#pragma unroll
                for (int m = 0; m < 11; m++) {
                    ffma2(acc[m][j], q[m].x, k0);
                    ffma2(acc[m][j], q[m].y, k1);
                }
            }
        }
#pragma unroll
        for (int j = 0; j < 2; j++) {
            int c = kb + lane + 32 * j;
#pragma unroll
            for (int m = 0; m < 11; m++)
                S[(w + 8 * m) * NPADS + c] = f2sum(acc[m][j]) * 0.125f;
        }
    }
    __syncthreads();

    // ---- Softmax + attn write ----
    const size_t attn_base = (g == 0 ? OFF_AI : OFF_AH);
    for (int rr = w; rr < RT; rr += 8) {
        int qr = r0 + rr;
        if (qr < N_) {
            float mx = -1e30f;
            for (int i = lane; i < N_; i += 32) mx = fmaxf(mx, S[rr * NPADS + i]);
#pragma unroll
            for (int o = 16; o; o >>= 1) mx = fmaxf(mx, __shfl_xor_sync(0xffffffffu, mx, o));
            float s = 0.0f;
            for (int i = lane; i < NPADS; i += 32) {
                if (i < N_) {
                    float e = __expf(S[rr * NPADS + i] - mx);
                    S[rr * NPADS + i] = e;
                    s += e;
                } else S[rr * NPADS + i] = 0.0f;
            }
#pragma unroll
            for (int o = 16; o; o >>= 1) s += __shfl_xor_sync(0xffffffffu, s, o);
            float inv = 1.0f / s;
            float* arow = outf + attn_base +
                ((((size_t)b * T_ + t) * L_ + l) * N_ + qr) * (size_t)N_;
            for (int i = lane; i < N_; i += 32) {
                float p = S[rr * NPADS + i] * inv;
                S[rr * NPADS + i] = p;
                arow[i] = p;
            }
        } else {
            for (int i = lane; i < NPADS; i += 32) S[rr * NPADS + i] = 0.0f;
        }
    }

    // ---- P2: PX = P @ x ----
    ull acc2[11] = {};
    for (int kc = 0; kc < 6; kc++) {
        const int kb = kc * 64;
        __syncthreads();
        for (int idx = tid; idx < 64 * 16; idx += 256) {
            int key = idx >> 4, d4 = idx & 15;
            int gk = kb + key;
            float4 v = make_float4(0.f, 0.f, 0.f, 0.f);
            if (gk < N_) v = *(const float4*)(xsrc + (size_t)gk * D_ + 4 * d4);
            int bs = key * KSTR + 4 * d4;
            *(float2*)&CH[bs]     = make_float2(v.x, v.y);
            *(float2*)&CH[bs + 2] = make_float2(v.z, v.w);
        }
        __syncthreads();
#pragma unroll 4
        for (int kk = 0; kk < 64; kk += 4) {
            float4 p[11];
#pragma unroll
            for (int m = 0; m < 11; m++)
                p[m] = *(const float4*)&S[(w + 8 * m) * NPADS + kb + kk];
            ull xv0 = *(const ull*)&CH[(kk)     * KSTR + 2 * lane];
            ull xv1 = *(const ull*)&CH[(kk + 1) * KSTR + 2 * lane];
            ull xv2 = *(const ull*)&CH[(kk + 2) * KSTR + 2 * lane];
            ull xv3 = *(const ull*)&CH[(kk + 3) * KSTR + 2 * lane];
#pragma unroll
            for (int m = 0; m < 11; m++) {
                ffma2(acc2[m], dup2(p[m].x), xv0);
                ffma2(acc2[m], dup2(p[m].y), xv1);
                ffma2(acc2[m], dup2(p[m].z), xv2);
                ffma2(acc2[m], dup2(p[m].w), xv3);
            }
        }
    }
    __syncthreads();   // all P reads done before Wt overwrites S
    // PX -> Qs (each warp writes only its own rows; halves are distinct cols)
#pragma unroll
    for (int m = 0; m < 11; m++) {
        float lo, hi;
        asm("mov.b64 {%0, %1}, %2;" : "=f"(lo), "=f"(hi) : "l"(acc2[m]));
        *(float2*)&Qs[(w + 8 * m) * QSTR + 2 * lane] = make_float2(lo, hi);
    }

    // ---- P3: O = PX @ Wv + bias -> g_O ----
    const float* W    = (g ? Wv_h : Wv_i) + (size_t)l * D_ * G_;
    const float* bias = (g ? b_h : b_i) + (size_t)l * G_;
    float* Wt = S;                     // 192 x 66 = 12672 <= 33792
    for (int idx = tid; idx < 64 * G_; idx += 256) {
        int d = idx / G_, c = idx % G_;
        Wt[c * KSTR + d] = W[d * G_ + c];
    }
    __syncthreads();

    float* Og = g_O[g] + (size_t)b * N_ * G_;
#pragma unroll
    for (int jg = 0; jg < 3; jg++) {
        ull acc3[11][2] = {};
#pragma unroll
        for (int d = 0; d < 64; d += 4) {
            ulonglong2 px[11];
#pragma unroll
            for (int m = 0; m < 11; m++)
                px[m] = *(const ulonglong2*)&Qs[(w + 8 * m) * QSTR + d];
#pragma unroll
            for (int j = 0; j < 2; j++) {
                const int c = jg * 64 + lane + 32 * j;
                ull w0 = *(const ull*)&Wt[c * KSTR + d];
                ull w1 = *(const ull*)&Wt[c * KSTR + d + 2];
#pragma unroll
                for (int m = 0; m < 11; m++) {
                    ffma2(acc3[m][j], px[m].x, w0);
                    ffma2(acc3[m][j], px[m].y, w1);
                }
            }
        }
#pragma unroll
        for (int m = 0; m < 11; m++) {
            int qr = r0 + w + 8 * m;
            if (qr < N_) {
#pragma unroll
                for (int j = 0; j < 2; j++) {
                    int col = jg * 64 + lane + 32 * j;
                    Og[(size_t)qr * G_ + col] = f2sum(acc3[m][j]) + __ldg(&bias[col]);
                }
            }
        }
    }
}

// ---------------------------------------------------------------------------
// K2: GRU gate + LayerNorm + next-stage Q/K. grid (9, 16), block 256.
// RT2=40 rows; warp w owns rows w+8m, m<5.
// ---------------------------------------------------------------------------
#define RT2    40
#define NT2    9
#define K2_WT  (RT2 * QSTR)                      // 2720
#define K2_SMEM_FLOATS (K2_WT + 4 * 64 * KSTR)   // 2720 + 16896 = 19616 -> 78,464 B

__global__ __launch_bounds__(256, 2)
void gate_qk_kernel(int t, int l, int do_gate, int do_qk, int l_next, int tx,
                    const float* __restrict__ x,
                    const float* __restrict__ Wq_i, const float* __restrict__ Wk_i,
                    const float* __restrict__ Wq_h, const float* __restrict__ Wk_h,
                    const float* __restrict__ ln_g, const float* __restrict__ ln_b,
                    float* __restrict__ outf) {
    extern __shared__ float sm[];
    float* Ys = sm;             // RT2 x QSTR
    float* Wt = sm + K2_WT;     // 4 x (64 x KSTR): Wq0, Wk0, Wq1, Wk1

    const int rt   = blockIdx.x;
    const int b    = blockIdx.y;
    const int tid  = threadIdx.x;
    const int w    = tid >> 5;
    const int lane = tid & 31;
    const int r0   = rt * RT2;

    if (do_gate) {
        for (int rr = w; rr < RT2; rr += 8) {
            int qr = r0 + rr;
            float o0 = 0.0f, o1 = 0.0f;
            float* hid = 0;
            if (qr < N_) {
                const float* oi = g_O[0] + ((size_t)b * N_ + qr) * G_;
                const float* oh = g_O[1] + ((size_t)b * N_ + qr) * G_;
                hid = outf + OFF_HID + (((size_t)b * L_ + l) * N_ + qr) * D_;
                int d0 = lane, d1 = lane + 32;
                float h0 = hid[d0], h1 = hid[d1];
                float rg0 = 1.0f / (1.0f + expf(-(oi[d0]       + oh[d0])));
                float ig0 = 1.0f / (1.0f + expf(-(oi[64 + d0]  + oh[64 + d0])));
                float ng0 = tanhf(oi[128 + d0] + rg0 * oh[128 + d0]);
                o0 = ng0 + ig0 * (h0 - ng0);
                float rg1 = 1.0f / (1.0f + expf(-(oi[d1]       + oh[d1])));
                float ig1 = 1.0f / (1.0f + expf(-(oi[64 + d1]  + oh[64 + d1])));
                float ng1 = tanhf(oi[128 + d1] + rg1 * oh[128 + d1]);
                o1 = ng1 + ig1 * (h1 - ng1);
            }
            float s = o0 + o1, q = o0 * o0 + o1 * o1;
#pragma unroll
            for (int off = 16; off; off >>= 1) {
                s += __shfl_xor_sync(0xffffffffu, s, off);
                q += __shfl_xor_sync(0xffffffffu, q, off);
            }
            if (qr < N_) {
                float mu  = s * (1.0f / 64.0f);
                float var = q * (1.0f / 64.0f) - mu * mu;
                float rs  = rsqrtf(var + 1e-5f);
                int d0 = lane, d1 = lane + 32;
                float y0 = (o0 - mu) * rs * __ldg(&ln_g[l * D_ + d0]) + __ldg(&ln_b[l * D_ + d0]);
                float y1 = (o1 - mu) * rs * __ldg(&ln_g[l * D_ + d1]) + __ldg(&ln_b[l * D_ + d1]);
                hid[d0] = y0; hid[d1] = y1;
                float* gx = g_X + ((size_t)b * N_ + qr) * D_;
                gx[d0] = y0; gx[d1] = y1;
                if (l == L_ - 1) {
                    float* po = outf + OFF_OUT + (((size_t)b * T_ + t) * N_ + qr) * D_;
                    po[d0] = y0; po[d1] = y1;
                }
                Ys[rr * QSTR + d0] = y0; Ys[rr * QSTR + d1] = y1;
            } else {
                Ys[rr * QSTR + lane] = 0.0f; Ys[rr * QSTR + lane + 32] = 0.0f;
            }
        }
    }

    if (!do_qk) return;
    __syncthreads();

    if (l_next == 0) {
        const float* xn = x + (((size_t)b * T_ + tx) * N_) * D_;
        for (int idx = tid; idx < RT2 * 64; idx += 256) {
            int r = idx >> 6, d = idx & 63;
            int qr = r0 + r;
            Ys[r * QSTR + d] = (qr < N_) ? xn[(size_t)qr * D_ + d] : 0.0f;
        }
    }
    // stage transposed weights: mat 0:Wq0 1:Wk0 2:Wq1 3:Wk1
    for (int idx = tid; idx < 4 * 64 * 64; idx += 256) {
        int mat = idx >> 12;
        int r = (idx >> 6) & 63, c = idx & 63;
        const float* Ws = (mat == 0) ? Wq_i : (mat == 1) ? Wk_i : (mat == 2) ? Wq_h : Wk_h;
        Wt[mat * (64 * KSTR) + c * KSTR + r] = Ws[(size_t)l_next * D_ * D_ + r * 64 + c];
    }
    __syncthreads();

#pragma unroll
    for (int g = 0; g < 2; g++) {
        const float* WtQ = Wt + (2 * g)     * (64 * KSTR);
        const float* WtK = Wt + (2 * g + 1) * (64 * KSTR);
        ull aq[5][2] = {}, ak[5][2] = {};
#pragma unroll
        for (int d = 0; d < 64; d += 4) {
            ulonglong2 y4[5];
#pragma unroll
            for (int m = 0; m < 5; m++)
                y4[m] = *(const ulonglong2*)&Ys[(w + 8 * m) * QSTR + d];
#pragma unroll
            for (int j = 0; j < 2; j++) {
                const int c = lane + 32 * j;
                ull wq0 = *(const ull*)&WtQ[c * KSTR + d];
                ull wq1 = *(const ull*)&WtQ[c * KSTR + d + 2];
                ull wk0 = *(const ull*)&WtK[c * KSTR + d];
                ull wk1 = *(const ull*)&WtK[c * KSTR + d + 2];
#pragma unroll
                for (int m = 0; m < 5; m++) {
                    ffma2(aq[m][j], y4[m].x, wq0);
                    ffma2(aq[m][j], y4[m].y, wq1);
                    ffma2(ak[m][j], y4[m].x, wk0);
                    ffma2(ak[m][j], y4[m].y, wk1);
                }
            }
        }
        float* Qd = g_Q[g] + (size_t)b * N_ * D_;
        float* Kd = g_K[g] + (size_t)b * N_ * D_;
#pragma unroll
        for (int m = 0; m < 5; m++) {
            int qr = r0 + w + 8 * m;
            if (qr < N_) {
#pragma unroll
                for (int j = 0; j < 2; j++) {
                    Qd[(size_t)qr * D_ + lane + 32 * j] = f2sum(aq[m][j]);
                    Kd[(size_t)qr * D_ + lane + 32 * j] = f2sum(ak[m][j]);
                }
            }
        }
    }
}

// ---------------------------------------------------------------------------
extern "C" void kernel_launch(void* const* d_in, const int* in_sizes, int n_in,
                              void* d_out, int out_size) {
    const float* x    = (const float*)d_in[0];
    const float* Wq_i = (const float*)d_in[1];
    const float* Wk_i = (const float*)d_in[2];
    const float* Wv_i = (const float*)d_in[3];
    const float* b_i  = (const float*)d_in[4];
    const float* Wq_h = (const float*)d_in[5];
    const float* Wk_h = (const float*)d_in[6];
    const float* Wv_h = (const float*)d_in[7];
    const float* b_h  = (const float*)d_in[8];
    const float* ln_g = (const float*)d_in[9];
    const float* ln_b = (const float*)d_in[10];
    float* outf = (float*)d_out;

    const int k1_smem = K1_SMEM_FLOATS * (int)sizeof(float);  // 176,000 B
    const int k2_smem = K2_SMEM_FLOATS * (int)sizeof(float);  //  78,464 B
    cudaFuncSetAttribute(attn_kernel, cudaFuncAttributeMaxDynamicSharedMemorySize, k1_smem);
    cudaFuncSetAttribute(gate_qk_kernel, cudaFuncAttributeMaxDynamicSharedMemorySize, k2_smem);

    zero_hidden_kernel<<<(int)((SZ_HID + 255) / 256), 256>>>(outf);

    dim3 k1_grid(NT, 2, 16);
    dim3 k2_grid(NT2, 16);

    // prologue: Q/K for stage (0,0) from x
    gate_qk_kernel<<<k2_grid, 256, k2_smem>>>(0, 0, /*do_gate*/0, /*do_qk*/1,
                                              /*l_next*/0, /*tx*/0, x,
                                              Wq_i, Wk_i, Wq_h, Wk_h, ln_g, ln_b, outf);

    for (int s = 0; s < T_ * L_; s++) {
        int t = s >> 1, l = s & 1;
        attn_kernel<<<k1_grid, 256, k1_smem>>>(t, l, (l == 0) ? 1 : 0, x,
                                               Wv_i, Wv_h, b_i, b_h, outf);
        gate_qk_kernel<<<k2_grid, 256, k2_smem>>>(t, l, 1, (s < T_ * L_ - 1) ? 1 : 0,
                                                  l ^ 1, t + 1, x,
                                                  Wq_i, Wk_i, Wq_h, Wk_h, ln_g, ln_b, outf);
    }
}

// round 10
// speedup vs baseline: 1.6082x; 1.3555x over previous
#include <cuda_runtime.h>
#include <cuda_bf16.h>
#include <math.h>

// Problem constants
#define B_  16
#define T_  12
#define N_  325
#define D_  64
#define L_  2
#define G_  192
#define BN  (B_ * N_)          // 5200

// d_out layout (floats): output, hidden, attn_input, attn_hidden
#define SZ_OUT ((size_t)B_ * T_ * N_ * D_)
#define SZ_HID ((size_t)B_ * L_ * N_ * D_)
#define SZ_A   ((size_t)B_ * T_ * L_ * N_ * N_)
#define OFF_OUT 0
#define OFF_HID (SZ_OUT)
#define OFF_AI  (SZ_OUT + SZ_HID)
#define OFF_AH  (SZ_OUT + SZ_HID + SZ_A)

// Scratch, parity double-buffered (stage s reads [s&1], writes [(s+1)&1])
__device__ float g_Xbuf[2][BN * D_];
__device__ float g_Qbuf[2][2][BN * D_];   // [parity][gat]
__device__ float g_Kbuf[2][2][BN * D_];

typedef unsigned long long ull;

__device__ __forceinline__ void ffma2(ull& d, ull a, ull b) {
    asm volatile("fma.rn.f32x2 %0, %1, %2, %0;" : "+l"(d) : "l"(a), "l"(b));
}
__device__ __forceinline__ float f2sum(ull v) {
    float lo, hi;
    asm("mov.b64 {%0, %1}, %2;" : "=f"(lo), "=f"(hi) : "l"(v));
    return lo + hi;
}
__device__ __forceinline__ ull dup2(float v) {
    ull r;
    asm("mov.b64 %0, {%1, %1};" : "=l"(r) : "f"(v));
    return r;
}
__device__ __forceinline__ void unpk(ull v, float& lo, float& hi) {
    asm("mov.b64 {%0, %1}, %2;" : "=f"(lo), "=f"(hi) : "l"(v));
}

// FMA-pipe exp (avoids MUFU bottleneck). x <= 0 here. ~1e-7 rel err.
__device__ __forceinline__ float fexp(float x) {
    float t = fmaxf(x * 1.4426950408889634f, -126.0f);
    float fi = floorf(t);
    float f = t - fi;
    float p =             1.535336188319500e-4f;
    p = fmaf(p, f, 1.339887440266574e-3f);
    p = fmaf(p, f, 9.618437357674640e-3f);
    p = fmaf(p, f, 5.550332471162809e-2f);
    p = fmaf(p, f, 2.402264791363012e-1f);
    p = fmaf(p, f, 6.931472028550421e-1f);
    p = fmaf(p, f, 1.0f);
    return p * __int_as_float(((int)fi + 127) << 23);
}

// ---------------------------------------------------------------------------
__global__ void zero_hidden_kernel(float* __restrict__ outf) {
    size_t i = (size_t)blockIdx.x * blockDim.x + threadIdx.x;
    if (i < SZ_HID) outf[OFF_HID + i] = 0.0f;
}

// ---------------------------------------------------------------------------
// Prologue: Q/K for stage (t=0,l=0) from x -> parity 0. grid (82,4), block 256.
// ---------------------------------------------------------------------------
__global__ void qk_prologue(const float* __restrict__ x,
                            const float* __restrict__ Wq_i, const float* __restrict__ Wk_i,
                            const float* __restrict__ Wq_h, const float* __restrict__ Wk_h) {
    __shared__ float Xs[64 * 68];
    __shared__ float Wt[64 * 66];

    const int rb  = blockIdx.x;
    const int cb  = blockIdx.y;
    const int tid = threadIdx.x;

    for (int idx = tid; idx < 64 * 64; idx += 256) {
        int r = idx >> 6, k = idx & 63;
        int row = rb * 64 + r;
        float v = 0.0f;
        if (row < BN) {
            int bb = row / N_, n = row - bb * N_;
            v = x[(((size_t)bb * T_) * N_ + n) * D_ + k];   // t = 0
        }
        Xs[r * 68 + k] = v;
    }

    const int g   = cb >> 1;
    const int isK = cb & 1;
    const float* W = (g ? (isK ? Wk_h : Wq_h) : (isK ? Wk_i : Wq_i)); // l = 0

    for (int idx = tid; idx < 64 * 64; idx += 256) {
        int k = idx >> 6, c = idx & 63;
        Wt[c * 66 + k] = W[k * 64 + c];
    }
    __syncthreads();

    const int ty = tid >> 4, tx = tid & 15;
    ull acc[4][4] = {};
#pragma unroll
    for (int k = 0; k < 64; k += 4) {
        ulonglong2 xv[4];
#pragma unroll
        for (int m = 0; m < 4; m++)
            xv[m] = *(const ulonglong2*)&Xs[(ty + 16 * m) * 68 + k];
#pragma unroll
        for (int j = 0; j < 4; j++) {
            const int c = tx + 16 * j;
            ull w0 = *(const ull*)&Wt[c * 66 + k];
            ull w1 = *(const ull*)&Wt[c * 66 + k + 2];
#pragma unroll
            for (int m = 0; m < 4; m++) {
                ffma2(acc[m][j], xv[m].x, w0);
                ffma2(acc[m][j], xv[m].y, w1);
            }
        }
    }

    float* dst = isK ? g_Kbuf[0][g] : g_Qbuf[0][g];
#pragma unroll
    for (int m = 0; m < 4; m++) {
        int row = rb * 64 + ty + 16 * m;
        if (row < BN) {
#pragma unroll
            for (int j = 0; j < 4; j++)
                dst[(size_t)row * 64 + tx + 16 * j] = f2sum(acc[m][j]);
        }
    }
}

// ---------------------------------------------------------------------------
// MEGA kernel: one launch per stage. grid (9, 16), block 512.
// Warps 0-7: input-gat, warps 8-15: hidden-gat.
// Warp in half: wr = wl&3 (row group: rows wr+4m, m<10), wc = wl>>2 (col half).
// ---------------------------------------------------------------------------
#define RT      40
#define NTILES  9
#define NPADS   384
#define QSTR    68
#define KSTR    66
#define QS_SZ   (RT * QSTR)          // 2720
#define S_SZ    (RT * NPADS)         // 15360
#define CH_SZ   (128 * KSTR)         // 8448
#define HALF_SZ (QS_SZ + S_SZ + CH_SZ)   // 26528
#define SMEM_FLOATS (2 * HALF_SZ)        // 53056 -> 212,224 B

__global__ __launch_bounds__(512)
void mega_kernel(int t, int l, int from_x, int do_qk, int l_next, int par,
                 const float* __restrict__ x,
                 const float* __restrict__ Wq_i, const float* __restrict__ Wk_i,
                 const float* __restrict__ Wv_i, const float* __restrict__ b_i,
                 const float* __restrict__ Wq_h, const float* __restrict__ Wk_h,
                 const float* __restrict__ Wv_h, const float* __restrict__ b_h,
                 const float* __restrict__ ln_g, const float* __restrict__ ln_b,
                 float* __restrict__ outf) {
    extern __shared__ float sm[];

    const int rt    = blockIdx.x;
    const int b     = blockIdx.y;
    const int tid   = threadIdx.x;
    const int half  = tid >> 8;          // gat index
    const int tid_h = tid & 255;
    const int wl    = tid_h >> 5;        // warp within half (0..7)
    const int wfull = tid >> 5;
    const int lane  = tid & 31;
    const int wr    = wl & 3;            // row group
    const int wc    = wl >> 2;           // col half
    const int r0    = rt * RT;

    float* base = sm + half * HALF_SZ;
    float* Qs = base;                    // Q -> PX
    float* S  = base + QS_SZ;            // scores/P -> weight staging
    float* CH = base + QS_SZ + S_SZ;     // K / x chunks -> O staging
    float* CH0 = sm + QS_SZ + S_SZ;
    float* CH1 = sm + HALF_SZ + QS_SZ + S_SZ;
    float* Ys  = sm;                     // shared y / x_{t+1} tile (half-0 Qs)

    const float* Qg = g_Qbuf[par][half] + (size_t)b * N_ * D_;
    const float* Kg = g_Kbuf[par][half] + (size_t)b * N_ * D_;
    const float* xsrc = from_x ? x + (((size_t)b * T_ + t) * N_) * D_
                               : g_Xbuf[par] + (size_t)b * N_ * D_;

    // ---- load Q tile ----
    for (int idx = tid_h; idx < RT * 64; idx += 256) {
        int r = idx >> 6, d = idx & 63;
        int qr = r0 + r;
        Qs[r * QSTR + d] = (qr < N_) ? Qg[(size_t)qr * D_ + d] : 0.0f;
    }

    // ---- Phase 1: S = Q K^T / 8 (10 rows/warp, 2 cols) ----
    const int c0off = (lane + 32 * (2 * wc))     * KSTR;
    const int c1off = (lane + 32 * (2 * wc + 1)) * KSTR;
    for (int kc = 0; kc < 3; kc++) {
        const int kb = kc * 128;
        __syncthreads();
        for (int idx = tid_h; idx < 128 * 16; idx += 256) {
            int key = idx >> 4, d4 = idx & 15;
            int gk = kb + key;
            float4 v = make_float4(0.f, 0.f, 0.f, 0.f);
            if (gk < N_) v = *(const float4*)(Kg + (size_t)gk * D_ + 4 * d4);
            int bs = key * KSTR + 4 * d4;
            *(float2*)&CH[bs]     = make_float2(v.x, v.y);
            *(float2*)&CH[bs + 2] = make_float2(v.z, v.w);
        }
        __syncthreads();

        ull acc[10][2] = {};
#pragma unroll
        for (int k = 0; k < 64; k += 4) {
            ull k00 = *(const ull*)&CH[c0off + k];
            ull k01 = *(const ull*)&CH[c0off + k + 2];
            ull k10 = *(const ull*)&CH[c1off + k];
            ull k11 = *(const ull*)&CH[c1off + k + 2];
#pragma unroll
            for (int h = 0; h < 2; h++) {
                ulonglong2 q[5];
#pragma unroll
                for (int mm = 0; mm < 5; mm++)
                    q[mm] = *(const ulonglong2*)&Qs[(wr + 4 * (5 * h + mm)) * QSTR + k];
#pragma unroll
                for (int mm = 0; mm < 5; mm++) {
                    const int m = 5 * h + mm;
                    ffma2(acc[m][0], q[mm].x, k00);
                    ffma2(acc[m][0], q[mm].y, k01);
                    ffma2(acc[m][1], q[mm].x, k10);
                    ffma2(acc[m][1], q[mm].y, k11);
                }
            }
        }
#pragma unroll
        for (int j = 0; j < 2; j++) {
            int c = kb + lane + 32 * (2 * wc + j);
#pragma unroll
            for (int m = 0; m < 10; m++)
                S[(wr + 4 * m) * NPADS + c] = f2sum(acc[m][j]) * 0.125f;
        }
    }
    __syncthreads();

    // ---- Softmax (poly exp) + write attn to d_out ----
    const size_t attn_base = (half == 0 ? OFF_AI : OFF_AH);
    for (int rr = wl; rr < RT; rr += 8) {
        int qr = r0 + rr;
        if (qr < N_) {
            float mx = -1e30f;
            for (int i = lane; i < N_; i += 32) mx = fmaxf(mx, S[rr * NPADS + i]);
#pragma unroll
            for (int o = 16; o; o >>= 1) mx = fmaxf(mx, __shfl_xor_sync(0xffffffffu, mx, o));
            float s = 0.0f;
            for (int i = lane; i < NPADS; i += 32) {
                if (i < N_) {
                    float e = fexp(S[rr * NPADS + i] - mx);
                    S[rr * NPADS + i] = e;
                    s += e;
                } else S[rr * NPADS + i] = 0.0f;
            }
#pragma unroll
            for (int o = 16; o; o >>= 1) s += __shfl_xor_sync(0xffffffffu, s, o);
            float inv = 1.0f / s;
            float* arow = outf + attn_base +
                ((((size_t)b * T_ + t) * L_ + l) * N_ + qr) * (size_t)N_;
            for (int i = lane; i < N_; i += 32) {
                float p = S[rr * NPADS + i] * inv;
                S[rr * NPADS + i] = p;
                arow[i] = p;
            }
        } else {
            for (int i = lane; i < NPADS; i += 32) S[rr * NPADS + i] = 0.0f;
        }
    }

    // ---- Phase 2: PX = P @ x (10 rows/warp, keys split by wc) ----
    ull acc2[10] = {};
    for (int kc = 0; kc < 3; kc++) {
        const int kb = kc * 128;
        __syncthreads();
        for (int idx = tid_h; idx < 128 * 16; idx += 256) {
            int key = idx >> 4, d4 = idx & 15;
            int gk = kb + key;
            float4 v = make_float4(0.f, 0.f, 0.f, 0.f);
            if (gk < N_) v = *(const float4*)(xsrc + (size_t)gk * D_ + 4 * d4);
            int bs = key * KSTR + 4 * d4;
            *(float2*)&CH[bs]     = make_float2(v.x, v.y);
            *(float2*)&CH[bs + 2] = make_float2(v.z, v.w);
        }
        __syncthreads();
        const int kof = wc * 64;
#pragma unroll 4
        for (int kk = 0; kk < 64; kk += 4) {
            ull xv0 = *(const ull*)&CH[(kof + kk)     * KSTR + 2 * lane];
            ull xv1 = *(const ull*)&CH[(kof + kk + 1) * KSTR + 2 * lane];
            ull xv2 = *(const ull*)&CH[(kof + kk + 2) * KSTR + 2 * lane];
            ull xv3 = *(const ull*)&CH[(kof + kk + 3) * KSTR + 2 * lane];
#pragma unroll
            for (int h = 0; h < 2; h++) {
                float4 p[5];
#pragma unroll
                for (int mm = 0; mm < 5; mm++)
                    p[mm] = *(const float4*)&S[(wr + 4 * (5 * h + mm)) * NPADS + kb + kof + kk];
#pragma unroll
                for (int mm = 0; mm < 5; mm++) {
                    const int m = 5 * h + mm;
                    ffma2(acc2[m], dup2(p[mm].x), xv0);
                    ffma2(acc2[m], dup2(p[mm].y), xv1);
                    ffma2(acc2[m], dup2(p[mm].z), xv2);
                    ffma2(acc2[m], dup2(p[mm].w), xv3);
                }
            }
        }
    }
    __syncthreads();
    // cross-wc reduction of PX partials via CH scratch
    if (wc == 1) {
#pragma unroll
        for (int m = 0; m < 10; m++) {
            float lo, hi;
            unpk(acc2[m], lo, hi);
            *(float2*)&CH[(wr + 4 * m) * 68 + 2 * lane] = make_float2(lo, hi);
        }
    }
    __syncthreads();
    if (wc == 0) {
#pragma unroll
        for (int m = 0; m < 10; m++) {
            float2 o = *(const float2*)&CH[(wr + 4 * m) * 68 + 2 * lane];
            float lo, hi;
            unpk(acc2[m], lo, hi);
            *(float2*)&Qs[(wr + 4 * m) * QSTR + 2 * lane] = make_float2(lo + o.x, hi + o.y);
        }
    }
    __syncthreads();

    // ---- Phase 3: O = PX @ Wv + bias -> CH (10 rows/warp, 3 col groups) ----
    {
        const float* W    = (half ? Wv_h : Wv_i) + (size_t)l * D_ * G_;
        const float* bias = (half ? b_h : b_i) + (size_t)l * G_;
        float* Wt = S;                       // [c][d] stride 66 (192*66 <= 15360)
        for (int idx = tid_h; idx < 64 * G_; idx += 256) {
            int d = idx / G_, c = idx % G_;
            Wt[c * KSTR + d] = W[d * G_ + c];
        }
        __syncthreads();

#pragma unroll
        for (int jg = 0; jg < 3; jg++) {
            const int c = (wc * 3 + jg) * 32 + lane;
            ull acc3[10] = {};
#pragma unroll
            for (int d = 0; d < 64; d += 4) {
                ull w0 = *(const ull*)&Wt[c * KSTR + d];
                ull w1 = *(const ull*)&Wt[c * KSTR + d + 2];
#pragma unroll
                for (int h = 0; h < 2; h++) {
                    ulonglong2 px[5];
#pragma unroll
                    for (int mm = 0; mm < 5; mm++)
                        px[mm] = *(const ulonglong2*)&Qs[(wr + 4 * (5 * h + mm)) * QSTR + d];
#pragma unroll
                    for (int mm = 0; mm < 5; mm++) {
                        const int m = 5 * h + mm;
                        ffma2(acc3[m], px[mm].x, w0);
                        ffma2(acc3[m], px[mm].y, w1);
                    }
                }
            }
            float bv = __ldg(&bias[c]);
#pragma unroll
            for (int m = 0; m < 10; m++)
                CH[(wr + 4 * m) * G_ + c] = f2sum(acc3[m]) + bv;
        }
    }
    __syncthreads();

    // ---- Gate: GRU + LayerNorm (all 16 warps, warp-per-row) ----
    for (int rr = wfull; rr < RT; rr += 16) {
        int qr = r0 + rr;
        float o0 = 0.0f, o1 = 0.0f;
        float* hid = 0;
        if (qr < N_) {
            const float* oi = CH0 + rr * G_;
            const float* oh = CH1 + rr * G_;
            hid = outf + OFF_HID + (((size_t)b * L_ + l) * N_ + qr) * D_;
            int d0 = lane, d1 = lane + 32;
            float h0 = hid[d0], h1 = hid[d1];
            float rg0 = 1.0f / (1.0f + expf(-(oi[d0]       + oh[d0])));
            float ig0 = 1.0f / (1.0f + expf(-(oi[64 + d0]  + oh[64 + d0])));
            float ng0 = tanhf(oi[128 + d0] + rg0 * oh[128 + d0]);
            o0 = ng0 + ig0 * (h0 - ng0);
            float rg1 = 1.0f / (1.0f + expf(-(oi[d1]       + oh[d1])));
            float ig1 = 1.0f / (1.0f + expf(-(oi[64 + d1]  + oh[64 + d1])));
            float ng1 = tanhf(oi[128 + d1] + rg1 * oh[128 + d1]);
            o1 = ng1 + ig1 * (h1 - ng1);
        }
        float s = o0 + o1, q = o0 * o0 + o1 * o1;
#pragma unroll
        for (int off = 16; off; off >>= 1) {
            s += __shfl_xor_sync(0xffffffffu, s, off);
            q += __shfl_xor_sync(0xffffffffu, q, off);
        }
        if (qr < N_) {
            float mu  = s * (1.0f / 64.0f);
            float var = q * (1.0f / 64.0f) - mu * mu;
            float rs  = rsqrtf(var + 1e-5f);
            int d0 = lane, d1 = lane + 32;
            float y0 = (o0 - mu) * rs * __ldg(&ln_g[l * D_ + d0]) + __ldg(&ln_b[l * D_ + d0]);
            float y1 = (o1 - mu) * rs * __ldg(&ln_g[l * D_ + d1]) + __ldg(&ln_b[l * D_ + d1]);
            hid[d0] = y0; hid[d1] = y1;
            float* gx = g_Xbuf[par ^ 1] + ((size_t)b * N_ + qr) * D_;
            gx[d0] = y0; gx[d1] = y1;
            if (l == L_ - 1) {
                float* po = outf + OFF_OUT + (((size_t)b * T_ + t) * N_ + qr) * D_;
                po[d0] = y0; po[d1] = y1;
            }
            Ys[rr * QSTR + d0] = y0; Ys[rr * QSTR + d1] = y1;
        } else {
            Ys[rr * QSTR + lane] = 0.0f; Ys[rr * QSTR + lane + 32] = 0.0f;
        }
    }

    // ---- Epilogue: Q/K for next stage (wc=0 -> Q, wc=1 -> K) ----
    if (do_qk) {
        __syncthreads();
        if (l_next == 0) {
            const float* xn = x + (((size_t)b * T_ + (t + 1)) * N_) * D_;
            for (int idx = tid; idx < RT * 64; idx += 512) {
                int r = idx >> 6, d = idx & 63;
                int qr = r0 + r;
                Ys[r * QSTR + d] = (qr < N_) ? xn[(size_t)qr * D_ + d] : 0.0f;
            }
        }
        const float* Wq = (half ? Wq_h : Wq_i) + (size_t)l_next * D_ * D_;
        const float* Wk = (half ? Wk_h : Wk_i) + (size_t)l_next * D_ * D_;
        for (int idx = tid_h; idx < 64 * 64; idx += 256) {
            int d = idx >> 6, c = idx & 63;
            S[c * KSTR + d]        = Wq[d * 64 + c];
            S[4224 + c * KSTR + d] = Wk[d * 64 + c];
        }
        __syncthreads();

        const float* Wsel = S + (wc ? 4224 : 0);
        ull aa[10][2] = {};
#pragma unroll
        for (int d = 0; d < 64; d += 4) {
            ull w00 = *(const ull*)&Wsel[(lane)      * KSTR + d];
            ull w01 = *(const ull*)&Wsel[(lane)      * KSTR + d + 2];
            ull w10 = *(const ull*)&Wsel[(lane + 32) * KSTR + d];
            ull w11 = *(const ull*)&Wsel[(lane + 32) * KSTR + d + 2];
#pragma unroll
            for (int h = 0; h < 2; h++) {
                ulonglong2 y4[5];
#pragma unroll
                for (int mm = 0; mm < 5; mm++)
                    y4[mm] = *(const ulonglong2*)&Ys[(wr + 4 * (5 * h + mm)) * QSTR + d];
#pragma unroll
                for (int mm = 0; mm < 5; mm++) {
                    const int m = 5 * h + mm;
                    ffma2(aa[m][0], y4[mm].x, w00);
                    ffma2(aa[m][0], y4[mm].y, w01);
                    ffma2(aa[m][1], y4[mm].x, w10);
                    ffma2(aa[m][1], y4[mm].y, w11);
                }
            }
        }
        float* Dd = (wc ? g_Kbuf[par ^ 1][half] : g_Qbuf[par ^ 1][half]) + (size_t)b * N_ * D_;
#pragma unroll
        for (int m = 0; m < 10; m++) {
            int qr = r0 + wr + 4 * m;
            if (qr < N_) {
                Dd[(size_t)qr * D_ + lane]      = f2sum(aa[m][0]);
                Dd[(size_t)qr * D_ + lane + 32] = f2sum(aa[m][1]);
            }
        }
    }
}

// ---------------------------------------------------------------------------
extern "C" void kernel_launch(void* const* d_in, const int* in_sizes, int n_in,
                              void* d_out, int out_size) {
    const float* x    = (const float*)d_in[0];
    const float* Wq_i = (const float*)d_in[1];
    const float* Wk_i = (const float*)d_in[2];
    const float* Wv_i = (const float*)d_in[3];
    const float* b_i  = (const float*)d_in[4];
    const float* Wq_h = (const float*)d_in[5];
    const float* Wk_h = (const float*)d_in[6];
    const float* Wv_h = (const float*)d_in[7];
    const float* b_h  = (const float*)d_in[8];
    const float* ln_g = (const float*)d_in[9];
    const float* ln_b = (const float*)d_in[10];
    float* outf = (float*)d_out;

    const int mega_smem = SMEM_FLOATS * (int)sizeof(float);   // 212,224 B
    cudaFuncSetAttribute(mega_kernel, cudaFuncAttributeMaxDynamicSharedMemorySize, mega_smem);

    zero_hidden_kernel<<<(int)((SZ_HID + 255) / 256), 256>>>(outf);
    qk_prologue<<<dim3(82, 4), 256>>>(x, Wq_i, Wk_i, Wq_h, Wk_h);

    dim3 mega_grid(NTILES, 16);
    for (int s = 0; s < T_ * L_; s++) {
        int t = s >> 1, l = s & 1;
        mega_kernel<<<mega_grid, 512, mega_smem>>>(
            t, l, (l == 0) ? 1 : 0, (s < T_ * L_ - 1) ? 1 : 0, l ^ 1, s & 1,
            x, Wq_i, Wk_i, Wv_i, b_i, Wq_h, Wk_h, Wv_h, b_h, ln_g, ln_b, outf);
    }
}